// round 4
// baseline (speedup 1.0000x reference)
#include <cuda_runtime.h>
#include <cuda_bf16.h>
#include <cuda_fp8.h>
#include <math.h>
#include <stdint.h>

#define NROWS 4096
#define HALF_N 2048
#define DD 512
#define INV_TAU 5.0f

#define KT 4                       // K chunks of 128 fp8
#define STAGE 16384                // 128 rows x 128 B per operand stage
#define OFFB 32768                 // B region after 2 A stages
#define SMEM_DYN 65536
#define GRID_GEMM 528

// ---- device-global scratch ----
__device__ __align__(16) uint8_t g_zn_f8[NROWS * DD];
__device__ float g_row_sum[NROWS];
__device__ float g_pos_acc;
__device__ unsigned int g_ctr;

// ============================================================
// K1: normalize rows of concat(z1,z2) -> e4m3; zero accumulators
// ============================================================
__global__ void k_normalize(const float* __restrict__ z1, const float* __restrict__ z2) {
    int row = blockIdx.x;
    const float* src = (row < HALF_N) ? (z1 + (size_t)row * DD)
                                      : (z2 + (size_t)(row - HALF_N) * DD);
    int t = threadIdx.x;
    float4 v = ((const float4*)src)[t];
    float ss = v.x * v.x + v.y * v.y + v.z * v.z + v.w * v.w;
    #pragma unroll
    for (int o = 16; o; o >>= 1) ss += __shfl_xor_sync(0xffffffffu, ss, o);

    __shared__ float warp_ss[4];
    __shared__ float s_inv;
    if ((t & 31) == 0) warp_ss[t >> 5] = ss;
    __syncthreads();
    if (t == 0) {
        float tot = warp_ss[0] + warp_ss[1] + warp_ss[2] + warp_ss[3];
        s_inv = 1.0f / fmaxf(sqrtf(tot), 1e-8f);
        g_row_sum[row] = 0.0f;
        if (row == 0) { g_pos_acc = 0.0f; g_ctr = 0u; }
    }
    __syncthreads();
    float inv = s_inv;
    __nv_fp8x2_storage_t p0 =
        __nv_cvt_float2_to_fp8x2(make_float2(v.x * inv, v.y * inv), __NV_SATFINITE, __NV_E4M3);
    __nv_fp8x2_storage_t p1 =
        __nv_cvt_float2_to_fp8x2(make_float2(v.z * inv, v.w * inv), __NV_SATFINITE, __NV_E4M3);
    uint32_t pk = (uint32_t)p0 | ((uint32_t)p1 << 16);
    ((uint32_t*)(g_zn_f8 + (size_t)row * DD))[t] = pk;
}

// ============================================================
// K2: symmetric fp8 GEMM + fused exp-sum epilogue + pos + finalize
// ============================================================
__device__ __forceinline__ void cp_async16(uint32_t saddr, const void* gptr) {
    asm volatile("cp.async.cg.shared.global [%0], [%1], 16;\n" :: "r"(saddr), "l"(gptr));
}
__device__ __forceinline__ void ldm_x4(uint32_t& r0, uint32_t& r1, uint32_t& r2, uint32_t& r3,
                                       uint32_t addr) {
    asm volatile("ldmatrix.sync.aligned.m8n8.x4.shared.b16 {%0,%1,%2,%3}, [%4];\n"
                 : "=r"(r0), "=r"(r1), "=r"(r2), "=r"(r3) : "r"(addr));
}
__device__ __forceinline__ void mma_fp8(float* c, uint32_t a0, uint32_t a1, uint32_t a2,
                                        uint32_t a3, uint32_t b0, uint32_t b1) {
    asm volatile("mma.sync.aligned.m16n8k32.row.col.f32.e4m3.e4m3.f32 "
                 "{%0,%1,%2,%3}, {%4,%5,%6,%7}, {%8,%9}, {%0,%1,%2,%3};\n"
                 : "+f"(c[0]), "+f"(c[1]), "+f"(c[2]), "+f"(c[3])
                 : "r"(a0), "r"(a1), "r"(a2), "r"(a3), "r"(b0), "r"(b1));
}

__global__ void __launch_bounds__(512, 1) k_simgemm(float* __restrict__ out) {
    extern __shared__ uint8_t dsm[];
    __shared__ float s_red[16];
    __shared__ int s_last;
    uint32_t sm_u = (uint32_t)__cvta_generic_to_shared(dsm);

    // linear block id -> (bm, bn), bm <= bn
    int idx = blockIdx.x;
    int bm = 0, rl = 32;
    while (idx >= rl) { idx -= rl; bm++; rl--; }
    int bn = bm + idx;
    bool diag = (bm == bn);
    bool isPos = (bn == bm + 16);

    int tid = threadIdx.x;
    int lane = tid & 31, warp = tid >> 5;
    int wm = warp >> 2, wn = warp & 3;        // 4x4 warp grid, 32x32 warp tiles

    // ---- loader per-thread geometry (2 x 16B per operand per stage) ----
    int u0 = tid, u1 = tid + 512;
    int lr0 = u0 >> 3, lc0 = u0 & 7;
    int lr1 = u1 >> 3, lc1 = u1 & 7;
    uint32_t dA0 = sm_u + (uint32_t)(lr0 * 128 + ((lc0 ^ (lr0 & 7)) << 4));
    uint32_t dA1 = sm_u + (uint32_t)(lr1 * 128 + ((lc1 ^ (lr1 & 7)) << 4));
    uint32_t dB0 = dA0 + OFFB, dB1 = dA1 + OFFB;
    const uint8_t* gA0 = g_zn_f8 + ((size_t)(bm * 128 + lr0) << 9) + lc0 * 16;
    const uint8_t* gA1 = g_zn_f8 + ((size_t)(bm * 128 + lr1) << 9) + lc1 * 16;
    const uint8_t* gB0 = g_zn_f8 + ((size_t)(bn * 128 + lr0) << 9) + lc0 * 16;
    const uint8_t* gB1 = g_zn_f8 + ((size_t)(bn * 128 + lr1) << 9) + lc1 * 16;

#define PREFETCH(s, kt_) do {                                    \
        uint32_t so_ = (uint32_t)(s) * STAGE;                    \
        int ko_ = (kt_) * 128;                                   \
        cp_async16(dA0 + so_, gA0 + ko_);                        \
        cp_async16(dA1 + so_, gA1 + ko_);                        \
        cp_async16(dB0 + so_, gB0 + ko_);                        \
        cp_async16(dB1 + so_, gB1 + ko_);                        \
        asm volatile("cp.async.commit_group;\n");                \
    } while (0)

    // ---- ldmatrix per-thread row geometry ----
    int rA0 = wm * 32 + (lane & 15);          // A rows, mt=0 / mt=1 (+16)
    int rA1 = rA0 + 16;
    int rB0 = wn * 32 + (lane & 7) + ((lane >> 4) << 3);   // B rows, ntp=0 / ntp=1 (+16)
    int rB1 = rB0 + 16;
    uint32_t bA0 = (uint32_t)(rA0 * 128), xA0 = (uint32_t)(rA0 & 7);
    uint32_t bA1 = (uint32_t)(rA1 * 128), xA1 = (uint32_t)(rA1 & 7);
    uint32_t bB0 = (uint32_t)(rB0 * 128) + OFFB, xB0 = (uint32_t)(rB0 & 7);
    uint32_t bB1 = (uint32_t)(rB1 * 128) + OFFB, xB1 = (uint32_t)(rB1 & 7);
    uint32_t cA = (uint32_t)(lane >> 4);          // column 16B-unit offsets
    uint32_t cB = (uint32_t)((lane >> 3) & 1);

    float acc[2][4][4];
    #pragma unroll
    for (int i = 0; i < 2; i++)
        #pragma unroll
        for (int j = 0; j < 4; j++)
            #pragma unroll
            for (int k = 0; k < 4; k++) acc[i][j][k] = 0.0f;

    PREFETCH(0, 0);

    #pragma unroll 1
    for (int kt = 0; kt < KT; kt++) {
        asm volatile("cp.async.wait_group 0;\n");
        __syncthreads();
        if (kt + 1 < KT) PREFETCH((kt + 1) & 1, kt + 1);
        uint32_t st = sm_u + (uint32_t)(kt & 1) * STAGE;

        #pragma unroll
        for (int kk = 0; kk < 4; kk++) {
            uint32_t c16a = (uint32_t)(kk * 2) + cA;
            uint32_t c16b = (uint32_t)(kk * 2) + cB;
            uint32_t a[2][4], b[4][2];
            ldm_x4(a[0][0], a[0][1], a[0][2], a[0][3], st + bA0 + ((c16a ^ xA0) << 4));
            ldm_x4(a[1][0], a[1][1], a[1][2], a[1][3], st + bA1 + ((c16a ^ xA1) << 4));
            ldm_x4(b[0][0], b[0][1], b[1][0], b[1][1], st + bB0 + ((c16b ^ xB0) << 4));
            ldm_x4(b[2][0], b[2][1], b[3][0], b[3][1], st + bB1 + ((c16b ^ xB1) << 4));
            #pragma unroll
            for (int mt = 0; mt < 2; mt++)
                #pragma unroll
                for (int nt = 0; nt < 4; nt++)
                    mma_fp8(acc[mt][nt], a[mt][0], a[mt][1], a[mt][2], a[mt][3],
                            b[nt][0], b[nt][1]);
        }
        __syncthreads();
    }
#undef PREFETCH

    // ---- epilogue: exp + per-row / per-col partials (smem-combined) ----
    float rowPart[2][2], colPart[4][2];
    float pos_l = 0.0f;
    #pragma unroll
    for (int i = 0; i < 2; i++) rowPart[i][0] = rowPart[i][1] = 0.0f;
    #pragma unroll
    for (int i = 0; i < 4; i++) colPart[i][0] = colPart[i][1] = 0.0f;

    #pragma unroll
    for (int mt = 0; mt < 2; mt++)
        #pragma unroll
        for (int nt = 0; nt < 4; nt++)
            #pragma unroll
            for (int j = 0; j < 4; j++) {
                float lg = acc[mt][nt][j] * INV_TAU;
                float e = __expf(lg);
                if (diag || isPos) {
                    int r = wm * 32 + mt * 16 + (lane >> 2) + (j >> 1) * 8;
                    int c = wn * 32 + nt * 8 + (lane & 3) * 2 + (j & 1);
                    if (r == c) {
                        if (diag) e = 0.0f;
                        else pos_l += lg;
                    }
                }
                rowPart[mt][j >> 1] += e;
                colPart[nt][j & 1] += e;
            }

    float* s_row = (float*)dsm;       // reuse operand smem (dead after mainloop)
    float* s_col = s_row + 128;
    if (tid < 256) s_row[tid] = 0.0f;
    __syncthreads();

    #pragma unroll
    for (int mt = 0; mt < 2; mt++)
        #pragma unroll
        for (int h = 0; h < 2; h++) {
            float v = rowPart[mt][h];
            v += __shfl_xor_sync(0xffffffffu, v, 1);
            v += __shfl_xor_sync(0xffffffffu, v, 2);
            if ((lane & 3) == 0)
                atomicAdd(&s_row[wm * 32 + mt * 16 + (lane >> 2) + h * 8], v);
        }
    if (!diag) {
        #pragma unroll
        for (int nt = 0; nt < 4; nt++)
            #pragma unroll
            for (int p = 0; p < 2; p++) {
                float v = colPart[nt][p];
                v += __shfl_xor_sync(0xffffffffu, v, 4);
                v += __shfl_xor_sync(0xffffffffu, v, 8);
                v += __shfl_xor_sync(0xffffffffu, v, 16);
                if (lane < 4)
                    atomicAdd(&s_col[wn * 32 + nt * 8 + (lane & 3) * 2 + p], v);
            }
    }
    if (isPos) {
        #pragma unroll
        for (int o = 16; o; o >>= 1) pos_l += __shfl_xor_sync(0xffffffffu, pos_l, o);
        if (lane == 0) atomicAdd(&g_pos_acc, pos_l);
    }
    __syncthreads();
    if (tid < 128)
        atomicAdd(&g_row_sum[bm * 128 + tid], s_row[tid]);
    else if (tid < 256 && !diag)
        atomicAdd(&g_row_sum[bn * 128 + (tid - 128)], s_col[tid - 128]);

    // ---- finalize: last CTA computes the loss ----
    __threadfence();
    __syncthreads();
    if (tid == 0) {
        unsigned prev = atomicAdd(&g_ctr, 1u);
        s_last = (prev == (unsigned)(GRID_GEMM - 1)) ? 1 : 0;
    }
    __syncthreads();
    if (s_last) {
        __threadfence();
        float ls = 0.0f;
        #pragma unroll 1
        for (int r = tid; r < NROWS; r += 512) ls += logf(__ldcg(&g_row_sum[r]));
        #pragma unroll
        for (int o = 16; o; o >>= 1) ls += __shfl_xor_sync(0xffffffffu, ls, o);
        if (lane == 0) s_red[warp] = ls;
        __syncthreads();
        if (tid == 0) {
            float tot = 0.0f;
            #pragma unroll
            for (int i = 0; i < 16; i++) tot += s_red[i];
            float pos2 = __ldcg(&g_pos_acc) * 2.0f;
            out[0] = (tot - pos2) * (1.0f / (float)NROWS);
        }
    }
}

extern "C" void kernel_launch(void* const* d_in, const int* in_sizes, int n_in,
                              void* d_out, int out_size) {
    const float* z1 = (const float*)d_in[0];
    const float* z2 = (const float*)d_in[1];
    float* out = (float*)d_out;
    cudaFuncSetAttribute(k_simgemm, cudaFuncAttributeMaxDynamicSharedMemorySize, SMEM_DYN);
    k_normalize<<<NROWS, 128>>>(z1, z2);
    k_simgemm<<<GRID_GEMM, 512, SMEM_DYN>>>(out);
}

// round 5
// speedup vs baseline: 1.3316x; 1.3316x over previous
#include <cuda_runtime.h>
#include <cuda_bf16.h>
#include <cuda_fp8.h>
#include <math.h>
#include <stdint.h>

#define NROWS 4096
#define HALF_N 2048
#define DD 512
#define INV_TAU 5.0f

#define CH 16384                   // one 128-row x 128B chunk
#define OFFB 65536                 // B ring after 4 resident A chunks
#define SMEM_DYN (131072 + 1024)
#define GRID_GEMM 144

// ---- device-global scratch ----
__device__ __align__(16) uint8_t g_zn_f8[NROWS * DD];
__device__ float g_row_sum[NROWS];
__device__ float g_pos_acc;
__device__ unsigned int g_ctr;

// ============================================================
// K1: normalize rows of concat(z1,z2) -> e4m3; zero accumulators
// ============================================================
__global__ void k_normalize(const float* __restrict__ z1, const float* __restrict__ z2) {
    int row = blockIdx.x;
    const float* src = (row < HALF_N) ? (z1 + (size_t)row * DD)
                                      : (z2 + (size_t)(row - HALF_N) * DD);
    int t = threadIdx.x;
    float4 v = ((const float4*)src)[t];
    float ss = v.x * v.x + v.y * v.y + v.z * v.z + v.w * v.w;
    #pragma unroll
    for (int o = 16; o; o >>= 1) ss += __shfl_xor_sync(0xffffffffu, ss, o);

    __shared__ float warp_ss[4];
    __shared__ float s_inv;
    if ((t & 31) == 0) warp_ss[t >> 5] = ss;
    __syncthreads();
    if (t == 0) {
        float tot = warp_ss[0] + warp_ss[1] + warp_ss[2] + warp_ss[3];
        s_inv = 1.0f / fmaxf(sqrtf(tot), 1e-8f);
        g_row_sum[row] = 0.0f;
        if (row == 0) { g_pos_acc = 0.0f; g_ctr = 0u; }
    }
    __syncthreads();
    float inv = s_inv;
    __nv_fp8x2_storage_t p0 =
        __nv_cvt_float2_to_fp8x2(make_float2(v.x * inv, v.y * inv), __NV_SATFINITE, __NV_E4M3);
    __nv_fp8x2_storage_t p1 =
        __nv_cvt_float2_to_fp8x2(make_float2(v.z * inv, v.w * inv), __NV_SATFINITE, __NV_E4M3);
    uint32_t pk = (uint32_t)p0 | ((uint32_t)p1 << 16);
    ((uint32_t*)(g_zn_f8 + (size_t)row * DD))[t] = pk;
}

// ============================================================
// K2: persistent fp8 GEMM, A resident, B ring, fused epilogue
// ============================================================
__device__ __forceinline__ void cp_async16(uint32_t saddr, const void* gptr) {
    asm volatile("cp.async.cg.shared.global [%0], [%1], 16;\n" :: "r"(saddr), "l"(gptr));
}
__device__ __forceinline__ void ldm_x4(uint32_t& r0, uint32_t& r1, uint32_t& r2, uint32_t& r3,
                                       uint32_t addr) {
    asm volatile("ldmatrix.sync.aligned.m8n8.x4.shared.b16 {%0,%1,%2,%3}, [%4];\n"
                 : "=r"(r0), "=r"(r1), "=r"(r2), "=r"(r3) : "r"(addr));
}
__device__ __forceinline__ void mma_fp8(float* c, uint32_t a0, uint32_t a1, uint32_t a2,
                                        uint32_t a3, uint32_t b0, uint32_t b1) {
    asm volatile("mma.sync.aligned.m16n8k32.row.col.f32.e4m3.e4m3.f32 "
                 "{%0,%1,%2,%3}, {%4,%5,%6,%7}, {%8,%9}, {%0,%1,%2,%3};\n"
                 : "+f"(c[0]), "+f"(c[1]), "+f"(c[2]), "+f"(c[3])
                 : "r"(a0), "r"(a1), "r"(a2), "r"(a3), "r"(b0), "r"(b1));
}

__global__ void __launch_bounds__(512, 1) k_persist(float* __restrict__ out) {
    extern __shared__ uint8_t dsm_raw[];
    __shared__ float s_red[16];
    __shared__ int s_last;
    uint32_t raw_u = (uint32_t)__cvta_generic_to_shared(dsm_raw);
    uint32_t sm_u = (raw_u + 1023u) & ~1023u;

    // ---- CTA -> (bm, group-of-4-bn) ----
    int idx = blockIdx.x, bm = 0, gj = 0;
    #pragma unroll 1
    for (bm = 0; bm < 32; bm++) {
        int G = (32 - bm + 3) >> 2;
        if (idx < G) { gj = idx; break; }
        idx -= G;
    }
    int bn0 = bm + gj * 4;
    int n_tiles = 32 - bn0; if (n_tiles > 4) n_tiles = 4;
    int total = n_tiles * 4;                  // 16KB stages overall

    int tid = threadIdx.x;
    int lane = tid & 31, warp = tid >> 5;
    int wm = warp >> 2, wn = warp & 3;        // 4x4 warp grid, 32x32 warp tiles

    // ---- loader geometry ----
    int lr = tid >> 3, lc = tid & 7;          // B stage: 1024 x 16B, 2 per thread
    int lr2 = lr + 64;
    uint32_t wB0 = sm_u + OFFB + (uint32_t)(lr * 128 + ((lc ^ (lr & 7)) << 4));
    uint32_t wB1 = sm_u + OFFB + (uint32_t)(lr2 * 128 + ((lc ^ (lr2 & 7)) << 4));
    const uint8_t* gBbase = g_zn_f8 + lc * 16;

    // ---- prologue: A resident (64KB, one group), then B stages 0..2 ----
    #pragma unroll
    for (int i = 0; i < 8; i++) {
        int u = tid + i * 512;                // 4096 x 16B
        int c = u >> 10, w = u & 1023, r = w >> 3, cc = w & 7;
        uint32_t dst = sm_u + c * CH + (uint32_t)(r * 128 + ((cc ^ (r & 7)) << 4));
        cp_async16(dst, g_zn_f8 + ((size_t)(bm * 128 + r) << 9) + c * 128 + cc * 16);
    }
    asm volatile("cp.async.commit_group;\n");
    #pragma unroll
    for (int g = 0; g < 3; g++) {             // total >= 4 always
        int bnB = (bn0 + (g >> 2)) * 128;
        int kB = (g & 3) * 128;
        cp_async16(wB0 + (uint32_t)((g & 3) * CH), gBbase + ((size_t)(bnB + lr) << 9) + kB);
        cp_async16(wB1 + (uint32_t)((g & 3) * CH), gBbase + ((size_t)(bnB + lr2) << 9) + kB);
        asm volatile("cp.async.commit_group;\n");
    }

    // ---- ldmatrix per-thread geometry (validated in round 4) ----
    int rA0 = wm * 32 + (lane & 15), rA1 = rA0 + 16;
    int rB0 = wn * 32 + (lane & 7) + ((lane >> 4) << 3), rB1 = rB0 + 16;
    uint32_t bA0 = (uint32_t)(rA0 * 128), xA0 = (uint32_t)(rA0 & 7);
    uint32_t bA1 = (uint32_t)(rA1 * 128), xA1 = (uint32_t)(rA1 & 7);
    uint32_t bB0 = (uint32_t)(rB0 * 128) + OFFB, xB0 = (uint32_t)(rB0 & 7);
    uint32_t bB1 = (uint32_t)(rB1 * 128) + OFFB, xB1 = (uint32_t)(rB1 & 7);
    uint32_t cA = (uint32_t)(lane >> 4);
    uint32_t cB = (uint32_t)((lane >> 3) & 1);

    float acc[2][4][4];
    #pragma unroll
    for (int i = 0; i < 2; i++)
        #pragma unroll
        for (int j = 0; j < 4; j++)
            #pragma unroll
            for (int k = 0; k < 4; k++) acc[i][j][k] = 0.0f;

    // ---- flat stage loop: stage f = tile (f>>2), chunk (f&3), buffer (f&3) ----
    #pragma unroll 1
    for (int f = 0; f < total; f++) {
        int rem = total - 1 - f;
        if (rem >= 2)      asm volatile("cp.async.wait_group 2;\n");
        else if (rem == 1) asm volatile("cp.async.wait_group 1;\n");
        else               asm volatile("cp.async.wait_group 0;\n");
        __syncthreads();
        int g = f + 3;
        if (g < total) {
            int bnB = (bn0 + (g >> 2)) * 128;
            int kB = (g & 3) * 128;
            cp_async16(wB0 + (uint32_t)((g & 3) * CH), gBbase + ((size_t)(bnB + lr) << 9) + kB);
            cp_async16(wB1 + (uint32_t)((g & 3) * CH), gBbase + ((size_t)(bnB + lr2) << 9) + kB);
            asm volatile("cp.async.commit_group;\n");
        }

        uint32_t so = sm_u + (uint32_t)((f & 3) * CH);   // A chunk == B buffer index
        #pragma unroll
        for (int kk = 0; kk < 4; kk++) {
            uint32_t c16a = (uint32_t)(kk * 2) + cA;
            uint32_t c16b = (uint32_t)(kk * 2) + cB;
            uint32_t a[2][4], b[4][2];
            ldm_x4(a[0][0], a[0][1], a[0][2], a[0][3], so + bA0 + ((c16a ^ xA0) << 4));
            ldm_x4(a[1][0], a[1][1], a[1][2], a[1][3], so + bA1 + ((c16a ^ xA1) << 4));
            ldm_x4(b[0][0], b[0][1], b[1][0], b[1][1], so + bB0 + ((c16b ^ xB0) << 4));
            ldm_x4(b[2][0], b[2][1], b[3][0], b[3][1], so + bB1 + ((c16b ^ xB1) << 4));
            #pragma unroll
            for (int mt = 0; mt < 2; mt++)
                #pragma unroll
                for (int nt = 0; nt < 4; nt++)
                    mma_fp8(acc[mt][nt], a[mt][0], a[mt][1], a[mt][2], a[mt][3],
                            b[nt][0], b[nt][1]);
        }

        if ((f & 3) == 3) {
            // ---- per-tile epilogue (no barriers; overlaps next tile's loads) ----
            int bn = bn0 + (f >> 2);
            bool diag = (bn == bm);
            bool isPos = (bn == bm + 16);
            float rowPart[2][2], colPart[4][2], pos_l = 0.0f;
            #pragma unroll
            for (int i = 0; i < 2; i++) rowPart[i][0] = rowPart[i][1] = 0.0f;
            #pragma unroll
            for (int i = 0; i < 4; i++) colPart[i][0] = colPart[i][1] = 0.0f;

            #pragma unroll
            for (int mt = 0; mt < 2; mt++)
                #pragma unroll
                for (int nt = 0; nt < 4; nt++)
                    #pragma unroll
                    for (int j = 0; j < 4; j++) {
                        float lg = acc[mt][nt][j] * INV_TAU;
                        float e = __expf(lg);
                        if (diag || isPos) {
                            int r = wm * 32 + mt * 16 + (lane >> 2) + (j >> 1) * 8;
                            int c = wn * 32 + nt * 8 + (lane & 3) * 2 + (j & 1);
                            if (r == c) {
                                if (diag) e = 0.0f;
                                else pos_l += lg;
                            }
                        }
                        rowPart[mt][j >> 1] += e;
                        colPart[nt][j & 1] += e;
                        acc[mt][nt][j] = 0.0f;
                    }

            #pragma unroll
            for (int mt = 0; mt < 2; mt++)
                #pragma unroll
                for (int h = 0; h < 2; h++) {
                    float v = rowPart[mt][h];
                    v += __shfl_xor_sync(0xffffffffu, v, 1);
                    v += __shfl_xor_sync(0xffffffffu, v, 2);
                    if ((lane & 3) == 0)
                        atomicAdd(&g_row_sum[bm * 128 + wm * 32 + mt * 16 + (lane >> 2) + h * 8], v);
                }
            if (!diag) {
                #pragma unroll
                for (int nt = 0; nt < 4; nt++)
                    #pragma unroll
                    for (int p = 0; p < 2; p++) {
                        float v = colPart[nt][p];
                        v += __shfl_xor_sync(0xffffffffu, v, 4);
                        v += __shfl_xor_sync(0xffffffffu, v, 8);
                        v += __shfl_xor_sync(0xffffffffu, v, 16);
                        if (lane < 4)
                            atomicAdd(&g_row_sum[bn * 128 + wn * 32 + nt * 8 + (lane & 3) * 2 + p], v);
                    }
            }
            if (isPos) {
                #pragma unroll
                for (int o = 16; o; o >>= 1) pos_l += __shfl_xor_sync(0xffffffffu, pos_l, o);
                if (lane == 0) atomicAdd(&g_pos_acc, pos_l);
            }
        }
    }

    // ---- finalize: last CTA computes the loss ----
    __threadfence();
    __syncthreads();
    if (tid == 0) {
        unsigned prev = atomicAdd(&g_ctr, 1u);
        s_last = (prev == (unsigned)(GRID_GEMM - 1)) ? 1 : 0;
    }
    __syncthreads();
    if (s_last) {
        __threadfence();
        float ls = 0.0f;
        #pragma unroll 1
        for (int r = tid; r < NROWS; r += 512) ls += logf(__ldcg(&g_row_sum[r]));
        #pragma unroll
        for (int o = 16; o; o >>= 1) ls += __shfl_xor_sync(0xffffffffu, ls, o);
        if (lane == 0) s_red[warp] = ls;
        __syncthreads();
        if (tid == 0) {
            float tot = 0.0f;
            #pragma unroll
            for (int i = 0; i < 16; i++) tot += s_red[i];
            float pos2 = __ldcg(&g_pos_acc) * 2.0f;
            out[0] = (tot - pos2) * (1.0f / (float)NROWS);
        }
    }
}

extern "C" void kernel_launch(void* const* d_in, const int* in_sizes, int n_in,
                              void* d_out, int out_size) {
    const float* z1 = (const float*)d_in[0];
    const float* z2 = (const float*)d_in[1];
    float* out = (float*)d_out;
    cudaFuncSetAttribute(k_persist, cudaFuncAttributeMaxDynamicSharedMemorySize, SMEM_DYN);
    k_normalize<<<NROWS, 128>>>(z1, z2);
    k_persist<<<GRID_GEMM, 512, SMEM_DYN>>>(out);
}

// round 6
// speedup vs baseline: 1.3672x; 1.0267x over previous
#include <cuda_runtime.h>
#include <cuda_bf16.h>
#include <cuda_fp8.h>
#include <math.h>
#include <stdint.h>

#define NROWS 4096
#define HALF_N 2048
#define DD 512
#define INV_TAU 5.0f

#define CH 16384                   // one 128-row x 128B chunk
#define OFFB 65536                 // B ring after 4 resident A chunks
#define SMEM_DYN (131072 + 1024)
#define GRID_GEMM 144

// ---- device-global scratch ----
__device__ __align__(16) uint8_t g_zn_f8[NROWS * DD];
__device__ float g_row_sum[NROWS];
__device__ float g_pos_acc;
__device__ unsigned int g_ctr;

// ============================================================
// K1: normalize rows of concat(z1,z2) -> e4m3; zero accumulators
// ============================================================
__global__ void k_normalize(const float* __restrict__ z1, const float* __restrict__ z2) {
    int row = blockIdx.x;
    const float* src = (row < HALF_N) ? (z1 + (size_t)row * DD)
                                      : (z2 + (size_t)(row - HALF_N) * DD);
    int t = threadIdx.x;
    float4 v = ((const float4*)src)[t];
    float ss = v.x * v.x + v.y * v.y + v.z * v.z + v.w * v.w;
    #pragma unroll
    for (int o = 16; o; o >>= 1) ss += __shfl_xor_sync(0xffffffffu, ss, o);

    __shared__ float warp_ss[4];
    __shared__ float s_inv;
    if ((t & 31) == 0) warp_ss[t >> 5] = ss;
    __syncthreads();
    if (t == 0) {
        float tot = warp_ss[0] + warp_ss[1] + warp_ss[2] + warp_ss[3];
        s_inv = 1.0f / fmaxf(sqrtf(tot), 1e-8f);
        g_row_sum[row] = 0.0f;
        if (row == 0) { g_pos_acc = 0.0f; g_ctr = 0u; }
    }
    __syncthreads();
    float inv = s_inv;
    __nv_fp8x2_storage_t p0 =
        __nv_cvt_float2_to_fp8x2(make_float2(v.x * inv, v.y * inv), __NV_SATFINITE, __NV_E4M3);
    __nv_fp8x2_storage_t p1 =
        __nv_cvt_float2_to_fp8x2(make_float2(v.z * inv, v.w * inv), __NV_SATFINITE, __NV_E4M3);
    uint32_t pk = (uint32_t)p0 | ((uint32_t)p1 << 16);
    ((uint32_t*)(g_zn_f8 + (size_t)row * DD))[t] = pk;
}

// ============================================================
// K2: persistent fp8 GEMM, A resident, B ring, pipelined frags
// ============================================================
__device__ __forceinline__ void cp_async16(uint32_t saddr, const void* gptr) {
    asm volatile("cp.async.cg.shared.global [%0], [%1], 16;\n" :: "r"(saddr), "l"(gptr));
}
__device__ __forceinline__ void ldm_x4(uint32_t& r0, uint32_t& r1, uint32_t& r2, uint32_t& r3,
                                       uint32_t addr) {
    asm volatile("ldmatrix.sync.aligned.m8n8.x4.shared.b16 {%0,%1,%2,%3}, [%4];\n"
                 : "=r"(r0), "=r"(r1), "=r"(r2), "=r"(r3) : "r"(addr));
}
__device__ __forceinline__ void mma_fp8(float* c, uint32_t a0, uint32_t a1, uint32_t a2,
                                        uint32_t a3, uint32_t b0, uint32_t b1) {
    asm volatile("mma.sync.aligned.m16n8k32.row.col.f32.e4m3.e4m3.f32 "
                 "{%0,%1,%2,%3}, {%4,%5,%6,%7}, {%8,%9}, {%0,%1,%2,%3};\n"
                 : "+f"(c[0]), "+f"(c[1]), "+f"(c[2]), "+f"(c[3])
                 : "r"(a0), "r"(a1), "r"(a2), "r"(a3), "r"(b0), "r"(b1));
}

__global__ void __launch_bounds__(512, 1) k_persist(float* __restrict__ out) {
    extern __shared__ uint8_t dsm_raw[];
    __shared__ float s_red[16];
    __shared__ int s_last;
    uint32_t raw_u = (uint32_t)__cvta_generic_to_shared(dsm_raw);
    uint32_t sm_u = (raw_u + 1023u) & ~1023u;

    // ---- CTA -> (bm, group-of-4-bn) ----
    int idx = blockIdx.x, bm = 0, gj = 0;
    #pragma unroll 1
    for (bm = 0; bm < 32; bm++) {
        int G = (32 - bm + 3) >> 2;
        if (idx < G) { gj = idx; break; }
        idx -= G;
    }
    int bn0 = bm + gj * 4;
    int n_tiles = 32 - bn0; if (n_tiles > 4) n_tiles = 4;
    int total = n_tiles * 4;

    int tid = threadIdx.x;
    int lane = tid & 31, warp = tid >> 5;
    int wm = warp >> 2, wn = warp & 3;        // 4x4 warp grid, 32x32 warp tiles

    // ---- loader geometry ----
    int lr = tid >> 3, lc = tid & 7;
    int lr2 = lr + 64;
    uint32_t wB0 = sm_u + OFFB + (uint32_t)(lr * 128 + ((lc ^ (lr & 7)) << 4));
    uint32_t wB1 = sm_u + OFFB + (uint32_t)(lr2 * 128 + ((lc ^ (lr2 & 7)) << 4));
    const uint8_t* gBbase = g_zn_f8 + lc * 16;

    // ---- prologue: A resident (64KB) + first 3 B stages ----
    #pragma unroll
    for (int i = 0; i < 8; i++) {
        int u = tid + i * 512;
        int c = u >> 10, w = u & 1023, r = w >> 3, cc = w & 7;
        uint32_t dst = sm_u + c * CH + (uint32_t)(r * 128 + ((cc ^ (r & 7)) << 4));
        cp_async16(dst, g_zn_f8 + ((size_t)(bm * 128 + r) << 9) + c * 128 + cc * 16);
    }
    asm volatile("cp.async.commit_group;\n");
    #pragma unroll
    for (int g = 0; g < 3; g++) {
        int bnB = (bn0 + (g >> 2)) * 128;
        int kB = (g & 3) * 128;
        cp_async16(wB0 + (uint32_t)((g & 3) * CH), gBbase + ((size_t)(bnB + lr) << 9) + kB);
        cp_async16(wB1 + (uint32_t)((g & 3) * CH), gBbase + ((size_t)(bnB + lr2) << 9) + kB);
        asm volatile("cp.async.commit_group;\n");
    }

    // ---- precomputed within-stage ldsm addresses: [kk][operand-half] ----
    int rA0 = wm * 32 + (lane & 15), rA1 = rA0 + 16;
    int rB0 = wn * 32 + (lane & 7) + ((lane >> 4) << 3), rB1 = rB0 + 16;
    uint32_t cA = (uint32_t)(lane >> 4);
    uint32_t cB = (uint32_t)((lane >> 3) & 1);
    uint32_t adA0[4], adA1[4], adB0[4], adB1[4];
    #pragma unroll
    for (int kk = 0; kk < 4; kk++) {
        adA0[kk] = (uint32_t)(rA0 * 128) + ((((uint32_t)(kk * 2) + cA) ^ (uint32_t)(rA0 & 7)) << 4);
        adA1[kk] = (uint32_t)(rA1 * 128) + ((((uint32_t)(kk * 2) + cA) ^ (uint32_t)(rA1 & 7)) << 4);
        adB0[kk] = (uint32_t)(rB0 * 128) + OFFB + ((((uint32_t)(kk * 2) + cB) ^ (uint32_t)(rB0 & 7)) << 4);
        adB1[kk] = (uint32_t)(rB1 * 128) + OFFB + ((((uint32_t)(kk * 2) + cB) ^ (uint32_t)(rB1 & 7)) << 4);
    }

    float acc[2][4][4];
    #pragma unroll
    for (int i = 0; i < 2; i++)
        #pragma unroll
        for (int j = 0; j < 4; j++)
            #pragma unroll
            for (int k = 0; k < 4; k++) acc[i][j][k] = 0.0f;

    uint32_t a[2][2][4], b[2][4][2];          // [pingpong][...]

    // ---- flat stage loop ----
    #pragma unroll 1
    for (int f = 0; f < total; f++) {
        int rem = total - 1 - f;
        if (rem >= 2)      asm volatile("cp.async.wait_group 2;\n");
        else if (rem == 1) asm volatile("cp.async.wait_group 1;\n");
        else               asm volatile("cp.async.wait_group 0;\n");
        __syncthreads();
        int g = f + 3;
        if (g < total) {
            int bnB = (bn0 + (g >> 2)) * 128;
            int kB = (g & 3) * 128;
            cp_async16(wB0 + (uint32_t)((g & 3) * CH), gBbase + ((size_t)(bnB + lr) << 9) + kB);
            cp_async16(wB1 + (uint32_t)((g & 3) * CH), gBbase + ((size_t)(bnB + lr2) << 9) + kB);
            asm volatile("cp.async.commit_group;\n");
        }

        uint32_t so = sm_u + (uint32_t)((f & 3) * CH);
        // prime kk=0 fragments
        ldm_x4(a[0][0][0], a[0][0][1], a[0][0][2], a[0][0][3], so + adA0[0]);
        ldm_x4(a[0][1][0], a[0][1][1], a[0][1][2], a[0][1][3], so + adA1[0]);
        ldm_x4(b[0][0][0], b[0][0][1], b[0][1][0], b[0][1][1], so + adB0[0]);
        ldm_x4(b[0][2][0], b[0][2][1], b[0][3][0], b[0][3][1], so + adB1[0]);

        #pragma unroll
        for (int kk = 0; kk < 4; kk++) {
            int cur = kk & 1, nxt = cur ^ 1;
            if (kk < 3) {                      // prefetch kk+1 before consuming kk
                ldm_x4(a[nxt][0][0], a[nxt][0][1], a[nxt][0][2], a[nxt][0][3], so + adA0[kk + 1]);
                ldm_x4(a[nxt][1][0], a[nxt][1][1], a[nxt][1][2], a[nxt][1][3], so + adA1[kk + 1]);
                ldm_x4(b[nxt][0][0], b[nxt][0][1], b[nxt][1][0], b[nxt][1][1], so + adB0[kk + 1]);
                ldm_x4(b[nxt][2][0], b[nxt][2][1], b[nxt][3][0], b[nxt][3][1], so + adB1[kk + 1]);
            }
            #pragma unroll
            for (int mt = 0; mt < 2; mt++)
                #pragma unroll
                for (int nt = 0; nt < 4; nt++)
                    mma_fp8(acc[mt][nt], a[cur][mt][0], a[cur][mt][1], a[cur][mt][2],
                            a[cur][mt][3], b[cur][nt][0], b[cur][nt][1]);
        }

        if ((f & 3) == 3) {
            // ---- per-tile epilogue (barrier-free) ----
            int bn = bn0 + (f >> 2);
            bool diag = (bn == bm);
            bool isPos = (bn == bm + 16);
            float rowPart[2][2], colPart[4][2], pos_l = 0.0f;
            #pragma unroll
            for (int i = 0; i < 2; i++) rowPart[i][0] = rowPart[i][1] = 0.0f;
            #pragma unroll
            for (int i = 0; i < 4; i++) colPart[i][0] = colPart[i][1] = 0.0f;

            #pragma unroll
            for (int mt = 0; mt < 2; mt++)
                #pragma unroll
                for (int nt = 0; nt < 4; nt++)
                    #pragma unroll
                    for (int j = 0; j < 4; j++) {
                        float lg = acc[mt][nt][j] * INV_TAU;
                        float e = __expf(lg);
                        if (diag || isPos) {
                            int r = wm * 32 + mt * 16 + (lane >> 2) + (j >> 1) * 8;
                            int c = wn * 32 + nt * 8 + (lane & 3) * 2 + (j & 1);
                            if (r == c) {
                                if (diag) e = 0.0f;
                                else pos_l += lg;
                            }
                        }
                        rowPart[mt][j >> 1] += e;
                        colPart[nt][j & 1] += e;
                        acc[mt][nt][j] = 0.0f;
                    }

            #pragma unroll
            for (int mt = 0; mt < 2; mt++)
                #pragma unroll
                for (int h = 0; h < 2; h++) {
                    float v = rowPart[mt][h];
                    v += __shfl_xor_sync(0xffffffffu, v, 1);
                    v += __shfl_xor_sync(0xffffffffu, v, 2);
                    if ((lane & 3) == 0)
                        atomicAdd(&g_row_sum[bm * 128 + wm * 32 + mt * 16 + (lane >> 2) + h * 8], v);
                }
            if (!diag) {
                #pragma unroll
                for (int nt = 0; nt < 4; nt++)
                    #pragma unroll
                    for (int p = 0; p < 2; p++) {
                        float v = colPart[nt][p];
                        v += __shfl_xor_sync(0xffffffffu, v, 4);
                        v += __shfl_xor_sync(0xffffffffu, v, 8);
                        v += __shfl_xor_sync(0xffffffffu, v, 16);
                        if (lane < 4)
                            atomicAdd(&g_row_sum[bn * 128 + wn * 32 + nt * 8 + (lane & 3) * 2 + p], v);
                    }
            }
            if (isPos) {
                #pragma unroll
                for (int o = 16; o; o >>= 1) pos_l += __shfl_xor_sync(0xffffffffu, pos_l, o);
                if (lane == 0) atomicAdd(&g_pos_acc, pos_l);
            }
        }
    }

    // ---- finalize: last CTA computes the loss ----
    __threadfence();
    __syncthreads();
    if (tid == 0) {
        unsigned prev = atomicAdd(&g_ctr, 1u);
        s_last = (prev == (unsigned)(GRID_GEMM - 1)) ? 1 : 0;
    }
    __syncthreads();
    if (s_last) {
        __threadfence();
        float ls = 0.0f;
        #pragma unroll 1
        for (int r = tid; r < NROWS; r += 512) ls += logf(__ldcg(&g_row_sum[r]));
        #pragma unroll
        for (int o = 16; o; o >>= 1) ls += __shfl_xor_sync(0xffffffffu, ls, o);
        if (lane == 0) s_red[warp] = ls;
        __syncthreads();
        if (tid == 0) {
            float tot = 0.0f;
            #pragma unroll
            for (int i = 0; i < 16; i++) tot += s_red[i];
            float pos2 = __ldcg(&g_pos_acc) * 2.0f;
            out[0] = (tot - pos2) * (1.0f / (float)NROWS);
        }
    }
}

extern "C" void kernel_launch(void* const* d_in, const int* in_sizes, int n_in,
                              void* d_out, int out_size) {
    const float* z1 = (const float*)d_in[0];
    const float* z2 = (const float*)d_in[1];
    float* out = (float*)d_out;
    cudaFuncSetAttribute(k_persist, cudaFuncAttributeMaxDynamicSharedMemorySize, SMEM_DYN);
    k_normalize<<<NROWS, 128>>>(z1, z2);
    k_persist<<<GRID_GEMM, 512, SMEM_DYN>>>(out);
}